// round 17
// baseline (speedup 1.0000x reference)
#include <cuda_runtime.h>
#include <math.h>

// ---------------------------------------------------------------------------
// CameraEstimator: camera[b] = sum_c x[b,c,:,:] * W[c]  (B=32768, C=256)
// then R[b] = nearest special-orthogonal matrix to camera[b].
//
// Warp-autonomous fused kernel: each warp streams its own sequence of
// b-tiles through a private 2-stage SMEM ring (cp.async.cg). Each LANE owns
// a contiguous 288B slice (8 channels x 9 elems -> compile-time j mapping),
// loads it, waits only its own group, reads only its own bytes. Zero
// __syncthreads / __syncwarp / mbarriers. Butterfly-reduce gives every lane
// the camera; lane k keeps tile k's camera in registers and solves it in
// the tail. Latency hiding via cp.async bytes in flight, not warp count.
//
// R = u1 v1^T + u2 v2^T + (u1 x u2)(v1 x v2)^T with v1,v2 top eigenvectors
// of M^T M, u_i = GS-normalized M v_i == reference u_flip @ vh.
// ---------------------------------------------------------------------------

#define MAXB 65536
#define WPB   2              // warps per block
#define TPB   64
#define NBLK  912            // 152 SMs x 6 blocks (smem: 6 x 36.9KB = 221KB)
#define GWTOT (NBLK * WPB)   // 1824 warps; nt = ceil(32768/1824) = 18 <= 32

__device__ float g_cam[MAXB * 9];   // fallback path only

static __device__ __forceinline__ unsigned smem_u32(const void* p) {
    unsigned a;
    asm("{ .reg .u64 t; cvta.to.shared.u64 t, %1; cvt.u32.u64 %0, t; }"
        : "=r"(a) : "l"(p));
    return a;
}
static __device__ __forceinline__ void cp16(unsigned dst, const void* src) {
    asm volatile("cp.async.cg.shared.global [%0], [%1], 16;"
                 :: "r"(dst), "l"(src) : "memory");
}
static __device__ __forceinline__ void cp_commit() {
    asm volatile("cp.async.commit_group;" ::: "memory");
}
template <int N>
static __device__ __forceinline__ void cp_wait() {
    asm volatile("cp.async.wait_group %0;" :: "n"(N) : "memory");
}

// ---------------- shared 3x3 Procrustes solve (fp32) ------------------------

__device__ __forceinline__ void bestNull(float a00, float a01, float a02,
                                         float a11, float a12, float a22,
                                         float lam, float& vx, float& vy, float& vz) {
    float b00 = a00 - lam, b11 = a11 - lam, b22 = a22 - lam;
    float c0x = a01 * a12 - a02 * b11;      // r0 x r1
    float c0y = a02 * a01 - b00 * a12;
    float c0z = b00 * b11 - a01 * a01;
    float c1x = a01 * b22 - a02 * a12;      // r0 x r2
    float c1y = a02 * a02 - b00 * b22;
    float c1z = b00 * a12 - a01 * a02;
    float c2x = b11 * b22 - a12 * a12;      // r1 x r2
    float c2y = a12 * a02 - a01 * b22;
    float c2z = a01 * a12 - b11 * a02;
    float n0 = c0x * c0x + c0y * c0y + c0z * c0z;
    float n1 = c1x * c1x + c1y * c1y + c1z * c1z;
    float n2 = c2x * c2x + c2y * c2y + c2z * c2z;
    float nx = c0x, ny = c0y, nz = c0z, nn = n0;
    if (n1 > nn) { nx = c1x; ny = c1y; nz = c1z; nn = n1; }
    if (n2 > nn) { nx = c2x; ny = c2y; nz = c2z; nn = n2; }
    if (nn < 1e-30f) { vx = 1.f; vy = 0.f; vz = 0.f; return; }
    float r = rsqrtf(nn);
    vx = nx * r; vy = ny * r; vz = nz * r;
}

__device__ __forceinline__ void perpOf(float vx, float vy, float vz,
                                       float& px, float& py, float& pz) {
    float ax = fabsf(vx), ay = fabsf(vy), az = fabsf(vz);
    float ex = 0.f, ey = 0.f, ez = 0.f;
    if (ax <= ay && ax <= az) ex = 1.f;
    else if (ay <= az)        ey = 1.f;
    else                      ez = 1.f;
    px = ey * vz - ez * vy;
    py = ez * vx - ex * vz;
    pz = ex * vy - ey * vx;
}

__device__ __forceinline__ void solve3x3(const float* __restrict__ m,
                                         float* __restrict__ o) {
    float m00 = m[0], m01 = m[1], m02 = m[2];
    float m10 = m[3], m11 = m[4], m12 = m[5];
    float m20 = m[6], m21 = m[7], m22 = m[8];

    float a00 = m00 * m00 + m10 * m10 + m20 * m20;
    float a01 = m00 * m01 + m10 * m11 + m20 * m21;
    float a02 = m00 * m02 + m10 * m12 + m20 * m22;
    float a11 = m01 * m01 + m11 * m11 + m21 * m21;
    float a12 = m01 * m02 + m11 * m12 + m21 * m22;
    float a22 = m02 * m02 + m12 * m12 + m22 * m22;

    float tr  = a00 + a11 + a22;
    float inv = (tr > 1e-30f) ? (1.0f / tr) : 0.f;
    a00 *= inv; a01 *= inv; a02 *= inv;
    a11 *= inv; a12 *= inv; a22 *= inv;

    float e2 = a00 * a11 + a00 * a22 + a11 * a22
             - a01 * a01 - a02 * a02 - a12 * a12;
    float dm = m00 * (m11 * m22 - m12 * m21)
             - m01 * (m10 * m22 - m12 * m20)
             + m02 * (m10 * m21 - m11 * m20);
    float e3 = (dm * dm) * (inv * inv * inv);

    float p2  = 1.0f - 3.0f * e2; if (p2 < 0.f) p2 = 0.f;
    float lam = (1.0f / 3.0f) + (2.0f / 3.0f) * sqrtf(p2);
#pragma unroll
    for (int it = 0; it < 8; ++it) {
        float f  = ((lam - 1.0f) * lam + e2) * lam - e3;
        float fp = (3.0f * lam - 2.0f) * lam + e2;
        lam -= f / (fp + 1e-30f);
    }
    float S = 1.0f - lam;
    float P = e2 - lam * S;
    float disc = S * S - 4.0f * P; if (disc < 0.f) disc = 0.f;
    float L2 = 0.5f * (S + sqrtf(disc));

    float v1x, v1y, v1z;
    bestNull(a00, a01, a02, a11, a12, a22, lam, v1x, v1y, v1z);

    float c2x, c2y, c2z;
    bestNull(a00, a01, a02, a11, a12, a22, L2, c2x, c2y, c2z);
    float dp = c2x * v1x + c2y * v1y + c2z * v1z;
    float v2x = c2x - dp * v1x, v2y = c2y - dp * v1y, v2z = c2z - dp * v1z;
    float n = v2x * v2x + v2y * v2y + v2z * v2z;
    if (n < 1e-12f) { perpOf(v1x, v1y, v1z, v2x, v2y, v2z);
                      n = v2x * v2x + v2y * v2y + v2z * v2z; }
    float rn = rsqrtf(n);
    v2x *= rn; v2y *= rn; v2z *= rn;
    float v3x = v1y * v2z - v1z * v2y;
    float v3y = v1z * v2x - v1x * v2z;
    float v3z = v1x * v2y - v1y * v2x;

    float u1x = m00 * v1x + m01 * v1y + m02 * v1z;
    float u1y = m10 * v1x + m11 * v1y + m12 * v1z;
    float u1z = m20 * v1x + m21 * v1y + m22 * v1z;
    n = u1x * u1x + u1y * u1y + u1z * u1z;
    if (n < 1e-30f) { u1x = 1.f; u1y = 0.f; u1z = 0.f; n = 1.f; }
    rn = rsqrtf(n); u1x *= rn; u1y *= rn; u1z *= rn;

    float t2x = m00 * v2x + m01 * v2y + m02 * v2z;
    float t2y = m10 * v2x + m11 * v2y + m12 * v2z;
    float t2z = m20 * v2x + m21 * v2y + m22 * v2z;
    dp = t2x * u1x + t2y * u1y + t2z * u1z;
    t2x -= dp * u1x; t2y -= dp * u1y; t2z -= dp * u1z;
    n = t2x * t2x + t2y * t2y + t2z * t2z;
    if (n < 1e-20f) { perpOf(u1x, u1y, u1z, t2x, t2y, t2z);
                      n = t2x * t2x + t2y * t2y + t2z * t2z; }
    rn = rsqrtf(n);
    float u2x = t2x * rn, u2y = t2y * rn, u2z = t2z * rn;
    float u3x = u1y * u2z - u1z * u2y;
    float u3y = u1z * u2x - u1x * u2z;
    float u3z = u1x * u2y - u1y * u2x;

    o[0] = u1x * v1x + u2x * v2x + u3x * v3x;
    o[1] = u1x * v1y + u2x * v2y + u3x * v3y;
    o[2] = u1x * v1z + u2x * v2z + u3x * v3z;
    o[3] = u1y * v1x + u2y * v2x + u3y * v3x;
    o[4] = u1y * v1y + u2y * v2y + u3y * v3y;
    o[5] = u1y * v1z + u2y * v2z + u3y * v3z;
    o[6] = u1z * v1x + u2z * v2x + u3z * v3x;
    o[7] = u1z * v1y + u2z * v2y + u3z * v3y;
    o[8] = u1z * v1z + u2z * v2z + u3z * v3z;
}

// ---------------- warp-autonomous fused kernel ------------------------------
__global__ __launch_bounds__(TPB) void fused_warp_kernel(const float* __restrict__ x,
                                                         const float* __restrict__ W,
                                                         float* __restrict__ out,
                                                         int Btot) {
    // per-warp 2-stage ring; lane owns bytes [288*lane, 288*lane+288) of a tile
    __shared__ __align__(16) float stg[WPB][2][2304];
    const int t    = threadIdx.x;
    const int lane = t & 31;
    const int wid  = t >> 5;
    const int gw   = blockIdx.x * WPB + wid;     // global warp id
    const int gwT  = gridDim.x * WPB;            // total warps

    // weights for this lane's 8 channels: W[8*lane .. 8*lane+7]
    float wreg[8];
    {
        float4 w0 = ((const float4*)W)[lane * 2];
        float4 w1 = ((const float4*)W)[lane * 2 + 1];
        wreg[0] = w0.x; wreg[1] = w0.y; wreg[2] = w0.z; wreg[3] = w0.w;
        wreg[4] = w1.x; wreg[5] = w1.y; wreg[6] = w1.z; wreg[7] = w1.w;
    }

    int nt = (gw < Btot) ? (Btot - gw + gwT - 1) / gwT : 0;   // tiles this warp owns

    const char*  src  = (const char*)x + (size_t)gw * 9216 + (size_t)lane * 288;
    const size_t strd = (size_t)gwT * 9216;
    unsigned sb0 = smem_u32(&stg[wid][0][0]) + (unsigned)lane * 288u;
    unsigned sb1 = sb0 + 9216u;

    // prologue: tiles 0,1 (one commit group per tile; empty groups are legal)
#pragma unroll
    for (int p = 0; p < 2; ++p) {
        if (p < nt) {
            unsigned d = p ? sb1 : sb0;
#pragma unroll
            for (int i = 0; i < 18; ++i) cp16(d + 16u * i, src + 16 * i);
        }
        cp_commit();
        src += strd;
    }

    float cam[9];
#pragma unroll
    for (int j = 0; j < 9; ++j) cam[j] = 0.f;

    int s = 0;
    for (int k = 0; k < nt; ++k) {
        cp_wait<1>();   // this lane's tile-k chunks landed (own data only)

        // accumulate this lane's 72 floats (8 channels x 9 elems, j compile-time)
        float acc[9];
#pragma unroll
        for (int j = 0; j < 9; ++j) acc[j] = 0.f;
        const float4* p4 = (const float4*)(&stg[wid][s][0] + lane * 72);
#pragma unroll
        for (int q = 0; q < 18; ++q) {
            float4 v = p4[q];
            float vr[4] = {v.x, v.y, v.z, v.w};
#pragma unroll
            for (int r = 0; r < 4; ++r) {
                const int f = 4 * q + r;          // 0..71
                acc[f % 9] += vr[r] * wreg[f / 9];
            }
        }

        // refill stage s with tile k+2 (this lane's region; reads above done)
        if (k + 2 < nt) {
            unsigned d = s ? sb1 : sb0;
#pragma unroll
            for (int i = 0; i < 18; ++i) cp16(d + 16u * i, src + 16 * i);
        }
        cp_commit();
        src += strd;

        // butterfly: every lane ends with the full 9 camera sums
#pragma unroll
        for (int off = 16; off > 0; off >>= 1)
#pragma unroll
            for (int j = 0; j < 9; ++j)
                acc[j] += __shfl_xor_sync(0xffffffffu, acc[j], off);

        if (lane == k) {
#pragma unroll
            for (int j = 0; j < 9; ++j) cam[j] = acc[j];
        }
        s ^= 1;
    }
    cp_wait<0>();

    // tail: lane k solves tile b = gw + k*gwT (camera already in registers)
    if (lane < nt) {
        float o[9];
        solve3x3(cam, o);
        float* op = out + ((size_t)gw + (size_t)lane * gwT) * 9;
#pragma unroll
        for (int j = 0; j < 9; ++j) op[j] = o[j];
    }
}

// ---------------- fallback path (unexpected shapes) -------------------------
__global__ void reduce_generic(const float* __restrict__ x, const float* __restrict__ W,
                               int B, int C) {
    int b = blockIdx.x * blockDim.x + threadIdx.x;
    if (b >= B) return;
    float acc[9];
#pragma unroll
    for (int j = 0; j < 9; ++j) acc[j] = 0.f;
    const float* p = x + (size_t)b * C * 9;
    for (int c = 0; c < C; ++c) {
        float wv = W[c];
#pragma unroll
        for (int j = 0; j < 9; ++j) acc[j] += p[c * 9 + j] * wv;
    }
#pragma unroll
    for (int j = 0; j < 9; ++j) g_cam[(size_t)b * 9 + j] = acc[j];
}

__global__ __launch_bounds__(128) void solve_kernel(float* __restrict__ out, int Btot) {
    int b = blockIdx.x * blockDim.x + threadIdx.x;
    if (b >= Btot) return;
    float mm[9];
#pragma unroll
    for (int j = 0; j < 9; ++j) mm[j] = g_cam[(size_t)b * 9 + j];
    float o[9];
    solve3x3(mm, o);
#pragma unroll
    for (int j = 0; j < 9; ++j) out[(size_t)b * 9 + j] = o[j];
}

// ---------------------------------------------------------------------------
extern "C" void kernel_launch(void* const* d_in, const int* in_sizes, int n_in,
                              void* d_out, int out_size) {
    const float* x = (const float*)d_in[0];
    const float* W = (const float*)d_in[1];
    float* out = (float*)d_out;

    int C = in_sizes[1];
    int B = in_sizes[0] / (C * 9);

    // fast path: nt per warp must fit in 32 lanes
    if (C == 256 && B <= GWTOT * 32 && B <= MAXB) {
        fused_warp_kernel<<<NBLK, TPB>>>(x, W, out, B);
    } else {
        if (B > MAXB) B = MAXB;
        reduce_generic<<<(B + 127) / 128, 128>>>(x, W, B, C);
        solve_kernel<<<(B + 127) / 128, 128>>>(out, B);
    }
}